// round 1
// baseline (speedup 1.0000x reference)
#include <cuda_runtime.h>

#define NB      8
#define NHEADS  12
#define HH      24          // H == W == 24
#define SEQ     576
#define DIM     64
#define NPOS    24
#define BATCH   96          // NB * NHEADS
#define KPAD    26          // smem row pad (float2-aligned, conflict-free with strided micro-tile)

// Scratch: pe_x_flat / pe_y_flat  [BATCH][SEQ][NPOS]
__device__ __align__(16) float g_Vx[BATCH * SEQ * NPOS];
__device__ __align__(16) float g_Vy[BATCH * SEQ * NPOS];

__device__ __forceinline__ float sigmoidf_(float x) {
    return 1.0f / (1.0f + __expf(-x));
}

__device__ __forceinline__ unsigned long long fma2(unsigned long long a,
                                                   unsigned long long b,
                                                   unsigned long long c) {
    unsigned long long d;
    asm("fma.rn.f32x2 %0, %1, %2, %3;" : "=l"(d) : "l"(a), "l"(b), "l"(c));
    return d;
}

__device__ __forceinline__ float fsqrt_approx(float x) {
    float r;
    asm("sqrt.approx.f32 %0, %1;" : "=f"(r) : "f"(x));
    return r;
}

// ---------------------------------------------------------------------------
// Kernel 1: CoPE units for both x and y paths.
// blockIdx.x in [0, 4608): path = blk/2304 (0 = x, 1 = y), id = blk % 2304.
// id = n*12 + m  (n in [0,192), m = head).
// Faithful-quirk attn decomposition: g = id -> (b_a, hd_a, r_a).
// ---------------------------------------------------------------------------
__global__ void __launch_bounds__(256) cope_kernel(
    const float* __restrict__ query,      // [8,12,576,64]
    const float* __restrict__ attn,       // [8,12,576,576]
    const float* __restrict__ pex,        // [64,24]
    const float* __restrict__ pey)        // [64,24]
{
    __shared__ float q_s[HH * DIM];       // 24 x 64
    __shared__ float pe_s[DIM * NPOS];    // 64 x 24
    __shared__ float li[HH * 25];         // logits_int, padded

    int blk  = blockIdx.x;
    int path = (blk >= 2304) ? 1 : 0;
    int id   = blk - path * 2304;
    int n    = id / 12;
    int m    = id % 12;
    // attn-side decomposition (faithful to reshape-without-permute)
    int b_a  = id / 288;
    int hd_a = (id / 24) % 12;
    int r_a  = id % 24;           // i (x-path) or j (y-path)
    // query-side decomposition
    int b_q  = n / 24;
    int s_q  = n % 24;            // i' (x-path) or j' (y-path)

    int t = threadIdx.x;

    const float* pe = path ? pey : pex;
    for (int idx = t; idx < DIM * NPOS; idx += 256)
        pe_s[idx] = pe[idx];

    if (!path) {
        // q_x rows: query[b_q, m, s_q*24 + j, :]  -> contiguous 24x64 block
        const float* qb = query + (((size_t)(b_q * 12 + m)) * SEQ + s_q * 24) * DIM;
        for (int idx = t; idx < HH * DIM; idx += 256)
            q_s[idx] = qb[idx];
    } else {
        // q_y rows: query[b_q, m, i*24 + s_q, :]  -> stride 24*64
        const float* qb = query + (((size_t)(b_q * 12 + m)) * SEQ + s_q) * DIM;
        for (int idx = t; idx < HH * DIM; idx += 256) {
            int rr = idx >> 6, d = idx & 63;
            q_s[idx] = qb[(size_t)rr * (24 * DIM) + d];
        }
    }
    __syncthreads();

    // logits_int[j][p] = sum_d q_s[j][d] * pe_s[d][p]
    for (int o = t; o < HH * NPOS; o += 256) {
        int j = o / NPOS, p = o % NPOS;
        float acc = 0.0f;
        #pragma unroll
        for (int d = 0; d < DIM; d++)
            acc = fmaf(q_s[j * DIM + d], pe_s[d * NPOS + p], acc);
        li[j * 25 + p] = acc;
    }
    __syncthreads();

    if (t < HH) {
        int j = t;   // row index (x-path: j over W; y-path: i over H)
        const float* arow;
        int astride;
        float* dst;
        if (!path) {
            // attn_x_flat[id-row]: attn[b_a, hd_a, r_a*24 + j, r_a*24 + k]
            arow = attn + (((size_t)(b_a * 12 + hd_a)) * SEQ + (size_t)(r_a * 24 + j)) * SEQ
                        + (size_t)(r_a * 24);
            astride = 1;
            int bh = b_q * 12 + m;
            int prow = s_q * 24 + j;
            dst = g_Vx + ((size_t)bh * SEQ + prow) * NPOS;
        } else {
            // attn_y_flat: attn[b_a, hd_a, i*24 + r_a, k*24 + r_a]  (i = j here)
            arow = attn + (((size_t)(b_a * 12 + hd_a)) * SEQ + (size_t)(j * 24 + r_a)) * SEQ
                        + (size_t)r_a;
            astride = 24;
            int bh = b_q * 12 + m;
            int prow = j * 24 + s_q;
            dst = g_Vy + ((size_t)bh * SEQ + prow) * NPOS;
        }
        // reverse cumsum of sigmoid + interpolated gather
        float pos = 0.0f;
        #pragma unroll
        for (int k = NPOS - 1; k >= 0; k--) {
            float gate = sigmoidf_(arow[k * astride]);
            pos += gate;
            float pp = fminf(pos, (float)(NPOS - 1));
            float pf = floorf(pp);
            int   ifl = (int)pf;
            int   ic  = (int)ceilf(pp);
            float w   = pp - pf;
            float v = li[j * 25 + ic] * w + li[j * 25 + ifl] * (1.0f - w);
            dst[k] = v;
        }
    }
}

// ---------------------------------------------------------------------------
// Kernel 2: fused double-cdist + mix.
// grid (9, 9, 96); block 256 = 16x16; each thread: 4x4 strided micro-tile.
// out[bz, p, q] = wx*||Vx_p - Vx_q|| + (1-wx)*||Vy_p - Vy_q||
// Gram form: d2 = nA + nB - 2*dot, dot via packed fma.rn.f32x2.
// ---------------------------------------------------------------------------
__global__ void __launch_bounds__(256) dist_kernel(
    const float* __restrict__ wxp,
    float* __restrict__ out)
{
    __shared__ __align__(16) float sA[2][64 * KPAD];
    __shared__ __align__(16) float sB[2][64 * KPAD];
    __shared__ float nA[2][64];
    __shared__ float nB[2][64];

    int bz = blockIdx.z;
    int p0 = blockIdx.y * 64;
    int q0 = blockIdx.x * 64;
    int t  = threadIdx.x;
    int tx = t & 15;
    int ty = t >> 4;

    // Load 64x24 row blocks (contiguous in global) for both arrays / both sides.
    #pragma unroll
    for (int s = 0; s < 2; s++) {
        const float* V = s ? g_Vy : g_Vx;
        const float4* ga = (const float4*)(V + ((size_t)bz * SEQ + p0) * NPOS);
        const float4* gb = (const float4*)(V + ((size_t)bz * SEQ + q0) * NPOS);
        for (int idx = t; idx < 64 * NPOS / 4; idx += 256) {  // 384 float4
            float4 va = ga[idx];
            float4 vb = gb[idx];
            int r = idx / 6, c = (idx % 6) * 4;
            float* da = &sA[s][r * KPAD + c];
            da[0] = va.x; da[1] = va.y; da[2] = va.z; da[3] = va.w;
            float* db = &sB[s][r * KPAD + c];
            db[0] = vb.x; db[1] = vb.y; db[2] = vb.z; db[3] = vb.w;
        }
    }
    __syncthreads();

    // Row norms: 256 tasks = 2 arrays x {A,B} x 64 rows
    {
        int s  = (t >> 7) & 1;
        int ab = (t >> 6) & 1;
        int r  = t & 63;
        const float* src = ab ? &sB[s][r * KPAD] : &sA[s][r * KPAD];
        float acc = 0.0f;
        #pragma unroll
        for (int k = 0; k < NPOS; k++)
            acc = fmaf(src[k], src[k], acc);
        if (ab) nB[s][r] = acc; else nA[s][r] = acc;
    }
    __syncthreads();

    float wxv = *wxp;
    float part[16];

    #pragma unroll
    for (int s = 0; s < 2; s++) {
        unsigned long long acc[16];
        #pragma unroll
        for (int u = 0; u < 16; u++) acc[u] = 0ull;

        const float* As = sA[s];
        const float* Bs = sB[s];
        #pragma unroll
        for (int kk = 0; kk < NPOS / 2; kk++) {
            unsigned long long a[4], b[4];
            #pragma unroll
            for (int i = 0; i < 4; i++)
                a[i] = *(const unsigned long long*)(As + (ty + 16 * i) * KPAD + 2 * kk);
            #pragma unroll
            for (int j = 0; j < 4; j++)
                b[j] = *(const unsigned long long*)(Bs + (tx + 16 * j) * KPAD + 2 * kk);
            #pragma unroll
            for (int i = 0; i < 4; i++)
                #pragma unroll
                for (int j = 0; j < 4; j++)
                    acc[i * 4 + j] = fma2(a[i], b[j], acc[i * 4 + j]);
        }

        float scale = s ? (1.0f - wxv) : wxv;
        #pragma unroll
        for (int i = 0; i < 4; i++) {
            float na = nA[s][ty + 16 * i];
            #pragma unroll
            for (int j = 0; j < 4; j++) {
                float2 g = *(float2*)&acc[i * 4 + j];
                float G = g.x + g.y;
                float d2 = fmaf(-2.0f, G, na + nB[s][tx + 16 * j]);
                d2 = fmaxf(d2, 0.0f);
                float d = fsqrt_approx(d2);
                if (s == 0) part[i * 4 + j] = scale * d;
                else        part[i * 4 + j] = fmaf(scale, d, part[i * 4 + j]);
            }
        }
    }

    // Write 64x64 tile (coalesced 16-wide segments per (i,j))
    #pragma unroll
    for (int i = 0; i < 4; i++) {
        int p = p0 + ty + 16 * i;
        float* orow = out + ((size_t)bz * SEQ + p) * SEQ;
        #pragma unroll
        for (int j = 0; j < 4; j++) {
            int q = q0 + tx + 16 * j;
            float o = part[i * 4 + j];
            if (p == q) o = 0.0f;   // exact-zero diagonal, matches clamped reference
            orow[q] = o;
        }
    }
}

// ---------------------------------------------------------------------------
extern "C" void kernel_launch(void* const* d_in, const int* in_sizes, int n_in,
                              void* d_out, int out_size) {
    const float* query = (const float*)d_in[0];
    const float* attn  = (const float*)d_in[1];
    const float* pex   = (const float*)d_in[2];
    const float* pey   = (const float*)d_in[3];
    const float* wx    = (const float*)d_in[4];
    float* out = (float*)d_out;

    cope_kernel<<<4608, 256>>>(query, attn, pex, pey);

    dim3 grid(SEQ / 64, SEQ / 64, BATCH);   // (9, 9, 96)
    dist_kernel<<<grid, 256>>>(wx, out);
}

// round 2
// speedup vs baseline: 1.4692x; 1.4692x over previous
#include <cuda_runtime.h>

#define NB      8
#define NHEADS  12
#define HH      24          // H == W == 24
#define SEQ     576
#define DIM     64
#define NPOS    24
#define BATCH   96          // NB * NHEADS
#define KPAD    26          // smem row pad (float2-aligned, conflict-free with strided micro-tile)

// Scratch: pe_x_flat / pe_y_flat  [BATCH][SEQ][NPOS]
__device__ __align__(16) float g_Vx[BATCH * SEQ * NPOS];
__device__ __align__(16) float g_Vy[BATCH * SEQ * NPOS];

__device__ __forceinline__ float sigmoidf_(float x) {
    return 1.0f / (1.0f + __expf(-x));
}

__device__ __forceinline__ unsigned long long fma2(unsigned long long a,
                                                   unsigned long long b,
                                                   unsigned long long c) {
    unsigned long long d;
    asm("fma.rn.f32x2 %0, %1, %2, %3;" : "=l"(d) : "l"(a), "l"(b), "l"(c));
    return d;
}

__device__ __forceinline__ float fsqrt_approx(float x) {
    float r;
    asm("sqrt.approx.f32 %0, %1;" : "=f"(r) : "f"(x));
    return r;
}

// ---------------------------------------------------------------------------
// Kernel 1: CoPE units for both x and y paths.
// blockIdx.x in [0, 4608): path = blk/2304 (0 = x, 1 = y), id = blk % 2304.
// id = n*12 + m  (n in [0,192), m = head).
// Faithful-quirk attn decomposition: g = id -> (b_a, hd_a, r_a).
// Phase C: one warp per row, parallel sigmoid + shfl suffix-scan.
// ---------------------------------------------------------------------------
__global__ void __launch_bounds__(256) cope_kernel(
    const float* __restrict__ query,      // [8,12,576,64]
    const float* __restrict__ attn,       // [8,12,576,576]
    const float* __restrict__ pex,        // [64,24]
    const float* __restrict__ pey)        // [64,24]
{
    __shared__ float q_s[HH * DIM];       // 24 x 64
    __shared__ float pe_s[DIM * NPOS];    // 64 x 24
    __shared__ float li[HH * 25];         // logits_int, padded

    int blk  = blockIdx.x;
    int path = (blk >= 2304) ? 1 : 0;
    int id   = blk - path * 2304;
    int n    = id / 12;
    int m    = id % 12;
    // attn-side decomposition (faithful to reshape-without-permute)
    int b_a  = id / 288;
    int hd_a = (id / 24) % 12;
    int r_a  = id % 24;           // i (x-path) or j (y-path)
    // query-side decomposition
    int b_q  = n / 24;
    int s_q  = n % 24;            // i' (x-path) or j' (y-path)

    int t = threadIdx.x;

    const float* pe = path ? pey : pex;
    for (int idx = t; idx < DIM * NPOS; idx += 256)
        pe_s[idx] = pe[idx];

    if (!path) {
        // q_x rows: query[b_q, m, s_q*24 + j, :]  -> contiguous 24x64 block
        const float* qb = query + (((size_t)(b_q * 12 + m)) * SEQ + s_q * 24) * DIM;
        for (int idx = t; idx < HH * DIM; idx += 256)
            q_s[idx] = qb[idx];
    } else {
        // q_y rows: query[b_q, m, i*24 + s_q, :]  -> stride 24*64
        const float* qb = query + (((size_t)(b_q * 12 + m)) * SEQ + s_q) * DIM;
        for (int idx = t; idx < HH * DIM; idx += 256) {
            int rr = idx >> 6, d = idx & 63;
            q_s[idx] = qb[(size_t)rr * (24 * DIM) + d];
        }
    }
    __syncthreads();

    // logits_int[j][p] = sum_d q_s[j][d] * pe_s[d][p]
    for (int o = t; o < HH * NPOS; o += 256) {
        int j = o / NPOS, p = o % NPOS;
        float acc = 0.0f;
        #pragma unroll
        for (int d = 0; d < DIM; d++)
            acc = fmaf(q_s[j * DIM + d], pe_s[d * NPOS + p], acc);
        li[j * 25 + p] = acc;
    }
    __syncthreads();

    // Phase C: warp-per-row suffix scan. 8 warps cover 24 rows in 3 passes.
    int warp = t >> 5, lane = t & 31;
    int bh = b_q * 12 + m;
    for (int j = warp; j < HH; j += 8) {
        const float* arow;
        int astride;
        float* dst;
        if (!path) {
            // attn_x_flat[id-row]: attn[b_a, hd_a, r_a*24 + j, r_a*24 + k]
            arow = attn + (((size_t)(b_a * 12 + hd_a)) * SEQ + (size_t)(r_a * 24 + j)) * SEQ
                        + (size_t)(r_a * 24);
            astride = 1;
            dst = g_Vx + ((size_t)bh * SEQ + (size_t)(s_q * 24 + j)) * NPOS;
        } else {
            // attn_y_flat: attn[b_a, hd_a, i*24 + r_a, k*24 + r_a]  (i = j here)
            arow = attn + (((size_t)(b_a * 12 + hd_a)) * SEQ + (size_t)(j * 24 + r_a)) * SEQ
                        + (size_t)r_a;
            astride = 24;
            dst = g_Vy + ((size_t)bh * SEQ + (size_t)(j * 24 + s_q)) * NPOS;
        }
        float v = 0.0f;
        if (lane < NPOS)
            v = sigmoidf_(arow[lane * astride]);
        // inclusive suffix scan over lanes [k, 23]
        #pragma unroll
        for (int d = 1; d < 32; d <<= 1) {
            float tv = __shfl_down_sync(0xffffffffu, v, d);
            if (lane + d < NPOS) v += tv;
        }
        if (lane < NPOS) {
            float pp = fminf(v, (float)(NPOS - 1));
            float pf = floorf(pp);
            int   ifl = (int)pf;
            int   ic  = (int)ceilf(pp);
            float w   = pp - pf;
            float val = li[j * 25 + ic] * w + li[j * 25 + ifl] * (1.0f - w);
            dst[lane] = val;
        }
    }
}

// ---------------------------------------------------------------------------
// Kernel 2: fused double-cdist + mix, symmetric-tile version.
// grid (45, 96); block 256 = 16x16; each thread: 4x4 strided micro-tile.
// Tile pair (ti <= tj) decoded from blockIdx.x; off-diagonal tiles are
// mirrored via an smem-staged transpose.
// out[bz, p, q] = wx*||Vx_p - Vx_q|| + (1-wx)*||Vy_p - Vy_q||
// ---------------------------------------------------------------------------
__global__ void __launch_bounds__(256) dist_kernel(
    const float* __restrict__ wxp,
    float* __restrict__ out)
{
    __shared__ __align__(16) float sA[2][64 * KPAD];
    __shared__ __align__(16) float sB[2][64 * KPAD];
    __shared__ float nA[2][64];
    __shared__ float nB[2][64];
    __shared__ float sT[64 * 65];     // transpose staging

    int bz = blockIdx.y;
    // decode triangular tile pair (ti <= tj) from blockIdx.x in [0,45)
    int u = blockIdx.x;
    int ti = 0;
    #pragma unroll 1
    while (u >= (9 - ti)) { u -= (9 - ti); ti++; }
    int tj = ti + u;
    int p0 = ti * 64;
    int q0 = tj * 64;

    int t  = threadIdx.x;
    int tx = t & 15;
    int ty = t >> 4;

    // Load 64x24 row blocks (contiguous in global) for both arrays / both sides.
    #pragma unroll
    for (int s = 0; s < 2; s++) {
        const float* V = s ? g_Vy : g_Vx;
        const float4* ga = (const float4*)(V + ((size_t)bz * SEQ + p0) * NPOS);
        const float4* gb = (const float4*)(V + ((size_t)bz * SEQ + q0) * NPOS);
        for (int idx = t; idx < 64 * NPOS / 4; idx += 256) {  // 384 float4
            float4 va = ga[idx];
            float4 vb = gb[idx];
            int r = idx / 6, c = (idx % 6) * 4;
            float* da = &sA[s][r * KPAD + c];
            da[0] = va.x; da[1] = va.y; da[2] = va.z; da[3] = va.w;
            float* db = &sB[s][r * KPAD + c];
            db[0] = vb.x; db[1] = vb.y; db[2] = vb.z; db[3] = vb.w;
        }
    }
    __syncthreads();

    // Row norms: 256 tasks = 2 arrays x {A,B} x 64 rows
    {
        int s  = (t >> 7) & 1;
        int ab = (t >> 6) & 1;
        int r  = t & 63;
        const float* src = ab ? &sB[s][r * KPAD] : &sA[s][r * KPAD];
        float acc = 0.0f;
        #pragma unroll
        for (int k = 0; k < NPOS; k++)
            acc = fmaf(src[k], src[k], acc);
        if (ab) nB[s][r] = acc; else nA[s][r] = acc;
    }
    __syncthreads();

    float wxv = *wxp;
    float part[16];

    #pragma unroll
    for (int s = 0; s < 2; s++) {
        unsigned long long acc[16];
        #pragma unroll
        for (int u2 = 0; u2 < 16; u2++) acc[u2] = 0ull;

        const float* As = sA[s];
        const float* Bs = sB[s];
        #pragma unroll
        for (int kk = 0; kk < NPOS / 2; kk++) {
            unsigned long long a[4], b[4];
            #pragma unroll
            for (int i = 0; i < 4; i++)
                a[i] = *(const unsigned long long*)(As + (ty + 16 * i) * KPAD + 2 * kk);
            #pragma unroll
            for (int j = 0; j < 4; j++)
                b[j] = *(const unsigned long long*)(Bs + (tx + 16 * j) * KPAD + 2 * kk);
            #pragma unroll
            for (int i = 0; i < 4; i++)
                #pragma unroll
                for (int j = 0; j < 4; j++)
                    acc[i * 4 + j] = fma2(a[i], b[j], acc[i * 4 + j]);
        }

        float scale = s ? (1.0f - wxv) : wxv;
        #pragma unroll
        for (int i = 0; i < 4; i++) {
            float na = nA[s][ty + 16 * i];
            #pragma unroll
            for (int j = 0; j < 4; j++) {
                float2 g = *(float2*)&acc[i * 4 + j];
                float G = g.x + g.y;
                float d2 = fmaf(-2.0f, G, na + nB[s][tx + 16 * j]);
                d2 = fmaxf(d2, 0.0f);
                float d = fsqrt_approx(d2);
                if (s == 0) part[i * 4 + j] = scale * d;
                else        part[i * 4 + j] = fmaf(scale, d, part[i * 4 + j]);
            }
        }
    }

    // Exact-zero diagonal (only possible on diagonal tiles)
    #pragma unroll
    for (int i = 0; i < 4; i++)
        #pragma unroll
        for (int j = 0; j < 4; j++)
            if (p0 + ty + 16 * i == q0 + tx + 16 * j) part[i * 4 + j] = 0.0f;

    // Write primary tile (coalesced 16-wide segments per (i,j))
    #pragma unroll
    for (int i = 0; i < 4; i++) {
        int p = p0 + ty + 16 * i;
        float* orow = out + ((size_t)bz * SEQ + p) * SEQ;
        #pragma unroll
        for (int j = 0; j < 4; j++)
            orow[q0 + tx + 16 * j] = part[i * 4 + j];
    }

    // Mirror tile for off-diagonal pairs: smem-staged transpose, coalesced write
    if (ti != tj) {
        #pragma unroll
        for (int i = 0; i < 4; i++)
            #pragma unroll
            for (int j = 0; j < 4; j++)
                sT[(ty + 16 * i) * 65 + (tx + 16 * j)] = part[i * 4 + j];
        __syncthreads();
        #pragma unroll
        for (int i = 0; i < 4; i++) {
            int q = q0 + ty + 16 * i;
            float* orow = out + ((size_t)bz * SEQ + q) * SEQ;
            #pragma unroll
            for (int j = 0; j < 4; j++)
                orow[p0 + tx + 16 * j] = sT[(tx + 16 * j) * 65 + (ty + 16 * i)];
        }
    }
}

// ---------------------------------------------------------------------------
extern "C" void kernel_launch(void* const* d_in, const int* in_sizes, int n_in,
                              void* d_out, int out_size) {
    const float* query = (const float*)d_in[0];
    const float* attn  = (const float*)d_in[1];
    const float* pex   = (const float*)d_in[2];
    const float* pey   = (const float*)d_in[3];
    const float* wx    = (const float*)d_in[4];
    float* out = (float*)d_out;

    cope_kernel<<<4608, 256>>>(query, attn, pex, pey);

    dim3 grid(45, BATCH);   // triangular tile pairs x batches
    dist_kernel<<<grid, 256>>>(wx, out);
}